// round 15
// baseline (speedup 1.0000x reference)
#include <cuda_runtime.h>
#include <cuda_fp16.h>
#include <cstdint>
#include <cstddef>

// Problem constants
#define B_  4
#define N_  4096
#define H_  16
#define DH_ 64
#define M_  266
#define D_  1024
#define QKVW 3072
#define ROWS_ (B_*H_*N_)        // 262144
#define BN_   (B_*N_)           // 16384
#define MP_ 288                 // padded feature count
#define DP_ 80                  // padded head dim: 64 data + ones col + zeros

#define DN_    0.3535533906f
#define RATIO_ 0.0613139315f
#define EPS_F  1e-4f
#define EPS_LN 1e-5f

// ------------------------- scratch (device globals) -------------------------
__device__ float g_kdiag[ROWS_];
__device__ float g_krowmax[ROWS_];
__device__ float g_kmax[B_ * H_];
__device__ float g_rsV[B_ * H_ * DP_];

__device__ __half g_QKV[(size_t)BN_ * QKVW];          // fused Q|K|V output (fp16)
__device__ __half g_sfT[(size_t)B_ * H_ * MP_ * N_];  // sf^T [bh][m][n]
__device__ __half g_vT[(size_t)B_ * H_ * DP_ * N_];   // scaled V^T [bh][d][n]
__device__ __half g_cT[(size_t)B_ * H_ * DP_ * MP_];  // ctx^T [bh][d][m]
__device__ __half g_af[(size_t)BN_ * D_];             // attention out
__device__ __half g_o2h[(size_t)BN_ * D_];            // Wo output (fp16)
__device__ __half g_x16[(size_t)BN_ * D_];            // x fp16
__device__ __half g_WTqkv[(size_t)QKVW * D_];         // [Wq*DN|Wk*DN|Wv]^T fp16
__device__ __half g_WoT[(size_t)D_ * D_];             // Wo^T fp16
__device__ __half g_projh[MP_ * DH_];                 // proj fp16, zero-padded

// ------------------------- helpers ------------------------------------------
__device__ __forceinline__ uint32_t smem_u32(const void* p) {
    uint32_t a;
    asm("{ .reg .u64 t; cvta.to.shared.u64 t, %1; cvt.u32.u64 %0, t; }" : "=r"(a) : "l"(p));
    return a;
}
__device__ __forceinline__ void ldm_x4(uint32_t addr, uint32_t& r0, uint32_t& r1,
                                       uint32_t& r2, uint32_t& r3) {
    asm volatile("ldmatrix.sync.aligned.m8n8.x4.shared.b16 {%0,%1,%2,%3}, [%4];"
                 : "=r"(r0), "=r"(r1), "=r"(r2), "=r"(r3) : "r"(addr));
}
__device__ __forceinline__ void mma_fp16(float* c, const uint32_t* a, const uint32_t* b) {
    asm volatile(
        "mma.sync.aligned.m16n8k16.row.col.f32.f16.f16.f32 "
        "{%0,%1,%2,%3}, {%4,%5,%6,%7}, {%8,%9}, {%0,%1,%2,%3};"
        : "+f"(c[0]), "+f"(c[1]), "+f"(c[2]), "+f"(c[3])
        : "r"(a[0]), "r"(a[1]), "r"(a[2]), "r"(a[3]), "r"(b[0]), "r"(b[1]));
}
__device__ __forceinline__ void cp16(uint32_t saddr, const void* gptr) {
    asm volatile("cp.async.cg.shared.global [%0], [%1], 16;" :: "r"(saddr), "l"(gptr));
}
#define CP_COMMIT() asm volatile("cp.async.commit_group;" ::: "memory")
#define CP_WAIT(n)  asm volatile("cp.async.wait_group %0;" :: "n"(n) : "memory")

__device__ __forceinline__ uint32_t pack_half2(float a, float b) {
    __half2 t;
    t.x = __float2half(a);
    t.y = __float2half(b);
    return *reinterpret_cast<uint32_t*>(&t);
}

// ------------------------- prep kernels --------------------------------------
__global__ __launch_bounds__(256) void convert_x_h_kernel(const float* __restrict__ x,
                                                          __half* __restrict__ xh) {
    const size_t i = ((size_t)blockIdx.x * 256 + threadIdx.x) * 4;
    float4 v = *(const float4*)(x + i);
    uint2 o;
    o.x = pack_half2(v.x, v.y);
    o.y = pack_half2(v.z, v.w);
    *(uint2*)(xh + i) = o;
}

__global__ __launch_bounds__(1024) void transT_all_kernel(const float* __restrict__ W0,
                                                          const float* __restrict__ W1,
                                                          const float* __restrict__ W2,
                                                          const float* __restrict__ W3,
                                                          __half* __restrict__ WTqkv,
                                                          __half* __restrict__ WoT) {
    __shared__ float tile[32][33];
    const int z = blockIdx.z;
    const float* W = (z == 0) ? W0 : (z == 1) ? W1 : (z == 2) ? W2 : W3;
    __half* T = (z < 3) ? (WTqkv + (size_t)z * D_ * D_) : WoT;
    const float scale = (z < 2) ? DN_ : 1.f;

    const int n = blockIdx.x * 32 + threadIdx.x;
    const int k = blockIdx.y * 32 + threadIdx.y;
    tile[threadIdx.y][threadIdx.x] = W[(size_t)k * D_ + n];
    __syncthreads();
    const float v = tile[threadIdx.x][threadIdx.y] * scale;
    const int on = blockIdx.x * 32 + threadIdx.y;
    const int ok = blockIdx.y * 32 + threadIdx.x;
    T[(size_t)on * D_ + ok] = __float2half(v);
}

__global__ __launch_bounds__(256) void proj_pad_kernel(const float* __restrict__ proj,
                                                       __half* __restrict__ ph) {
    const int idx = blockIdx.x * 256 + threadIdx.x;
    if (idx >= MP_ * DH_) return;
    const int m = idx >> 6, k = idx & 63;
    ph[idx] = __float2half((m < M_) ? proj[m * 64 + k] : 0.f);
}

// ------ fp16 GEMM: CTA 128x128, 4 warps (2x2 of 64x64), 3-stage, 2 CTA/SM ---
#define KC    64
#define PITCH 144
#define GA_OPB (128 * PITCH)          // 18432
#define GF_STAGE (2 * GA_OPB)         // 36864
#define GF_SMEM (3 * GF_STAGE)        // 110592

template <typename OutT>
__global__ __launch_bounds__(128, 2) void gemm_fp16(
    const __half* __restrict__ A, const __half* __restrict__ Bm,
    OutT* __restrict__ C, int ldc) {
    extern __shared__ char smem[];
    const uint32_t sb = smem_u32(smem);
    const int tid = threadIdx.x;
    const int wid = tid >> 5;
    const int lid = tid & 31;
    const int warp_m = wid & 1;       // 0..1 (64 rows)
    const int warp_n = wid >> 1;      // 0..1 (64 cols)
    const int row0 = blockIdx.y * 128;
    const int col0 = blockIdx.x * 128;

    const __half* gA = A + (size_t)row0 * D_;
    const __half* gB = Bm + (size_t)col0 * D_;

    const uint32_t a_base = (uint32_t)((warp_m * 64 + (lid & 15)) * PITCH + (lid >> 4) * 16);
    const uint32_t b_base = (uint32_t)((warp_n * 64 + ((lid >> 4) * 8) + (lid & 7)) * PITCH +
                                       ((lid >> 3) & 1) * 16);

    float acc[4][8][4];
#pragma unroll
    for (int mi = 0; mi < 4; mi++)
#pragma unroll
        for (int ni = 0; ni < 8; ni++)
#pragma unroll
            for (int q = 0; q < 4; q++) acc[mi][ni][q] = 0.f;

    auto issue = [&](int c) {
        const uint32_t st = sb + (uint32_t)(c % 3) * GF_STAGE;
        const int k0 = c * KC;
        for (int i = tid; i < 1024; i += 128) {
            const int r = i >> 3, cc = i & 7;
            cp16(st + r * PITCH + cc * 16, gA + (size_t)r * D_ + k0 + cc * 8);
            cp16(st + GA_OPB + r * PITCH + cc * 16, gB + (size_t)r * D_ + k0 + cc * 8);
        }
    };

    issue(0); CP_COMMIT();
    issue(1); CP_COMMIT();

    for (int c = 0; c < D_ / KC; c++) {
        CP_WAIT(1);
        __syncthreads();
        if (c + 2 < D_ / KC) issue(c + 2);
        CP_COMMIT();

        const uint32_t st = sb + (uint32_t)(c % 3) * GF_STAGE;
#pragma unroll
        for (int ks = 0; ks < 4; ks++) {
            const uint32_t kb = ks * 32;
            uint32_t av[4][4];
#pragma unroll
            for (int mi = 0; mi < 4; mi++) {
                const uint32_t ao = a_base + mi * 16 * PITCH + kb;
                ldm_x4(st + ao, av[mi][0], av[mi][1], av[mi][2], av[mi][3]);
            }
#pragma unroll
            for (int p = 0; p < 4; p++) {
                uint32_t bv[2][2];
                const uint32_t bo = b_base + p * 16 * PITCH + kb;
                ldm_x4(st + GA_OPB + bo, bv[0][0], bv[0][1], bv[1][0], bv[1][1]);
#pragma unroll
                for (int mi = 0; mi < 4; mi++)
#pragma unroll
                    for (int nn = 0; nn < 2; nn++)
                        mma_fp16(acc[mi][p * 2 + nn], av[mi], bv[nn]);
            }
        }
    }

    const int g = lid >> 2, tg = lid & 3;
#pragma unroll
    for (int mi = 0; mi < 4; mi++) {
#pragma unroll
        for (int ni = 0; ni < 8; ni++) {
            const int row = row0 + warp_m * 64 + mi * 16 + g;
            const int col = col0 + warp_n * 64 + ni * 8 + tg * 2;
            if constexpr (sizeof(OutT) == 2) {
                *(uint32_t*)((__half*)C + (size_t)row * ldc + col) =
                    pack_half2(acc[mi][ni][0], acc[mi][ni][1]);
                *(uint32_t*)((__half*)C + (size_t)(row + 8) * ldc + col) =
                    pack_half2(acc[mi][ni][2], acc[mi][ni][3]);
            } else {
                float2 v0 = {acc[mi][ni][0], acc[mi][ni][1]};
                float2 v1 = {acc[mi][ni][2], acc[mi][ni][3]};
                *(float2*)((float*)C + (size_t)row * ldc + col) = v0;
                *(float2*)((float*)C + (size_t)(row + 8) * ldc + col) = v1;
            }
        }
    }
}

// ------------------------- K-feature via MMA ----------------------------------
#define FA_A  0
#define FA_B  GA_OPB                       // 18432
#define FA_DIAG (GA_OPB + MP_ * PITCH)     // 59904
#define FEAT_SMEM (FA_DIAG + 128 * 4)      // 60416
#define TPITCH 136

__global__ __launch_bounds__(256, 1) void kfeat_mma_kernel(
    const __half* __restrict__ QK, int ldq,
    const __half* __restrict__ projh,
    __half* __restrict__ fout,
    float* __restrict__ diag_out, float* __restrict__ rowmax_out) {
    extern __shared__ char smem[];
    const uint32_t sb = smem_u32(smem);
    float* diag_s = (float*)(smem + FA_DIAG);
    const int t = threadIdx.x;
    const int wid = t >> 5;
    const int lid = t & 31;
    const int bh = blockIdx.y;
    const int b = bh >> 4, h = bh & 15;
    const int n0 = blockIdx.x * 128;
    const size_t idx0 = (size_t)bh * N_ + n0;

    for (int i = t; i < 1024; i += 256) {
        const int r = i >> 3, seg = i & 7;
        *(uint4*)(smem + FA_A + r * PITCH + seg * 16) =
            *(const uint4*)(QK + ((size_t)(b * N_ + n0 + r)) * ldq + h * 64 + seg * 8);
    }
    for (int e = t; e < MP_ * 8; e += 256) {
        const int r = e >> 3, seg = e & 7;
        *(uint4*)(smem + FA_B + r * PITCH + seg * 16) =
            *(const uint4*)(projh + r * 64 + seg * 8);
    }
    __syncthreads();

    {
        const int row = t >> 1;
        const int halfsel = t & 1;
        const __half* rp = (const __half*)(smem + FA_A + row * PITCH) + halfsel * 32;
        float dsum = 0.f;
#pragma unroll
        for (int j = 0; j < 32; j++) {
            const float v = __half2float(rp[j]);
            dsum += v * v;
        }
        dsum += __shfl_xor_sync(0xffffffffu, dsum, 1);
        if (halfsel == 0) diag_s[row] = 0.5f * dsum;
    }
    __syncthreads();

    const uint32_t a_base = (uint32_t)((wid * 16 + (lid & 15)) * PITCH + (lid >> 4) * 16);
    const uint32_t b_base = (uint32_t)((((lid >> 4) * 8) + (lid & 7)) * PITCH +
                                       ((lid >> 3) & 1) * 16);

    float acc[36][4];
#pragma unroll
    for (int t2 = 0; t2 < 36; t2++)
#pragma unroll
        for (int q = 0; q < 4; q++) acc[t2][q] = 0.f;

#pragma unroll
    for (int ks = 0; ks < 4; ks++) {
        const uint32_t kb = ks * 32;
        uint32_t av[4];
        ldm_x4(sb + FA_A + a_base + kb, av[0], av[1], av[2], av[3]);
#pragma unroll
        for (int p = 0; p < 18; p++) {
            uint32_t bv[2][2];
            ldm_x4(sb + FA_B + b_base + p * 16 * PITCH + kb,
                   bv[0][0], bv[0][1], bv[1][0], bv[1][1]);
            mma_fp16(acc[2 * p], av, bv[0]);
            mma_fp16(acc[2 * p + 1], av, bv[1]);
        }
    }

    const int g = lid >> 2, tg = lid & 3;
    float r0 = -1e30f, r1 = -1e30f;
#pragma unroll
    for (int t2 = 0; t2 < 36; t2++) {
        const int m = t2 * 8 + tg * 2;
        if (m < M_)     { r0 = fmaxf(r0, acc[t2][0]); r1 = fmaxf(r1, acc[t2][2]); }
        if (m + 1 < M_) { r0 = fmaxf(r0, acc[t2][1]); r1 = fmaxf(r1, acc[t2][3]); }
    }
    r0 = fmaxf(r0, __shfl_xor_sync(0xffffffffu, r0, 1));
    r0 = fmaxf(r0, __shfl_xor_sync(0xffffffffu, r0, 2));
    r1 = fmaxf(r1, __shfl_xor_sync(0xffffffffu, r1, 1));
    r1 = fmaxf(r1, __shfl_xor_sync(0xffffffffu, r1, 2));

    const int rowa = wid * 16 + g;
    const int rowb = rowa + 8;

    if (tg == 0) {
        rowmax_out[idx0 + rowa] = r0;
        rowmax_out[idx0 + rowb] = r1;
        diag_out[idx0 + rowa] = diag_s[rowa];
        diag_out[idx0 + rowb] = diag_s[rowb];
    }
    __half* sT = (__half*)smem;
#pragma unroll
    for (int p = 0; p < 2; p++) {
        __syncthreads();
#pragma unroll
        for (int t2 = 18 * p; t2 < 18 * p + 18; t2++) {
            const int m = t2 * 8 + tg * 2;
            const int mloc = m - p * 144;
            const float v0 = (m < M_)     ? expf(acc[t2][0] - r0) : 0.f;
            const float v1 = (m + 1 < M_) ? expf(acc[t2][1] - r0) : 0.f;
            const float v2 = (m < M_)     ? expf(acc[t2][2] - r1) : 0.f;
            const float v3 = (m + 1 < M_) ? expf(acc[t2][3] - r1) : 0.f;
            sT[mloc * TPITCH + rowa] = __float2half(v0);
            sT[(mloc + 1) * TPITCH + rowa] = __float2half(v1);
            sT[mloc * TPITCH + rowb] = __float2half(v2);
            sT[(mloc + 1) * TPITCH + rowb] = __float2half(v3);
        }
        __syncthreads();
        for (int i = t; i < 2304; i += 256) {
            const int r = i >> 4, cseg = i & 15;
            *(uint4*)(fout + ((size_t)bh * MP_ + p * 144 + r) * N_ + n0 + cseg * 8) =
                *(uint4*)(sT + r * TPITCH + cseg * 8);
        }
    }
}

__global__ __launch_bounds__(256) void kmax_reduce_kernel(const float* __restrict__ rowmax,
                                                          float* __restrict__ kmax) {
    __shared__ float sm[256];
    const int bh = blockIdx.x;
    float v = -1e30f;
    for (int i = threadIdx.x; i < N_; i += 256)
        v = fmaxf(v, rowmax[bh * N_ + i]);
    sm[threadIdx.x] = v;
    __syncthreads();
#pragma unroll
    for (int off = 128; off > 0; off >>= 1) {
        if (threadIdx.x < off) sm[threadIdx.x] = fmaxf(sm[threadIdx.x], sm[threadIdx.x + off]);
        __syncthreads();
    }
    if (threadIdx.x == 0) kmax[bh] = sm[0];
}

__global__ __launch_bounds__(256) void vconvT_kernel(const __half* __restrict__ V, int ldv,
                                                     const float* __restrict__ kdiag,
                                                     const float* __restrict__ rowmax,
                                                     const float* __restrict__ kmax,
                                                     float* __restrict__ rsV,
                                                     __half* __restrict__ vT) {
    __shared__ float sm[64][33];
    __shared__ float scale_s[32];
    __shared__ float dsum[DP_];
    const int bh = blockIdx.y;
    const int b = bh >> 4, h = bh & 15;
    const int n0 = blockIdx.x * 32;
    const int t = threadIdx.x;

#pragma unroll
    for (int q = 0; q < 8; q++) {
        const int idx = t + q * 256;
        const int d = idx & 63, j = idx >> 6;
        sm[d][j] = __half2float(V[((size_t)(b * N_ + n0 + j)) * ldv + h * 64 + d]);
    }
    if (t < 32) {
        const size_t ni = (size_t)bh * N_ + n0 + t;
        scale_s[t] = expf(rowmax[ni] - kdiag[ni] - kmax[bh]);
    }
    __syncthreads();

#pragma unroll
    for (int q = 0; q < 10; q++) {
        const int idx = t + q * 256;
        const int j = idx & 31, dd = idx >> 5;
        const float raw = (dd < 64) ? sm[dd][j] : ((dd == 64) ? 1.f : 0.f);
        float s = raw;
#pragma unroll
        for (int off = 16; off > 0; off >>= 1) s += __shfl_xor_sync(0xffffffffu, s, off);
        if (j == 0) dsum[dd] = s;
        vT[((size_t)bh * DP_ + dd) * N_ + n0 + j] = __float2half(raw * scale_s[j]);
    }
    __syncthreads();
    if (t < DP_) atomicAdd(&rsV[bh * DP_ + t], dsum[t]);
}

// ------------------------- ctx MMA ------------------------------------------
#define CTX_PITCH 144
#define CTX_AOPB (96 * CTX_PITCH)
#define CTX_BOPB (80 * CTX_PITCH)
#define CTX_STAGE (CTX_AOPB + CTX_BOPB)
#define CTX_SMEM (3 * CTX_STAGE)

__global__ __launch_bounds__(192, 1) void ctx_mma_kernel(
    const __half* __restrict__ sfT, const __half* __restrict__ vT,
    const float* __restrict__ rsV, __half* __restrict__ cT) {
    extern __shared__ char smem[];
    const uint32_t sb = smem_u32(smem);
    const int tid = threadIdx.x;
    const int wid = tid >> 5;
    const int lid = tid & 31;
    const int bh = blockIdx.y;
    const int m0 = blockIdx.x * 96;

    const __half* gA = sfT + ((size_t)bh * MP_ + m0) * N_;
    const __half* gB = vT + (size_t)bh * DP_ * N_;

    const uint32_t a_base = (uint32_t)((wid * 16 + (lid & 15)) * CTX_PITCH + (lid >> 4) * 16);
    const uint32_t b_base = (uint32_t)((((lid >> 4) * 8) + (lid & 7)) * CTX_PITCH +
                                       ((lid >> 3) & 1) * 16);

    float acc[10][4];
#pragma unroll
    for (int t2 = 0; t2 < 10; t2++)
#pragma unroll
        for (int q = 0; q < 4; q++) acc[t2][q] = 0.f;

    auto issue = [&](int c) {
        const uint32_t st = sb + (uint32_t)(c % 3) * CTX_STAGE;
        const int k0 = c * 64;
        for (int i = tid; i < 768; i += 192) {
            const int r = i >> 3, cc = i & 7;
            cp16(st + r * CTX_PITCH + cc * 16, gA + (size_t)r * N_ + k0 + cc * 8);
        }
        for (int i = tid; i < 640; i += 192) {
            const int r = i >> 3, cc = i & 7;
            cp16(st + CTX_AOPB + r * CTX_PITCH + cc * 16, gB + (size_t)r * N_ + k0 + cc * 8);
        }
    };

    issue(0); CP_COMMIT();
    issue(1); CP_COMMIT();

    for (int c = 0; c < N_ / 64; c++) {
        CP_WAIT(1);
        __syncthreads();
        if (c + 2 < N_ / 64) issue(c + 2);
        CP_COMMIT();

        const uint32_t st = sb + (uint32_t)(c % 3) * CTX_STAGE;
#pragma unroll
        for (int ks = 0; ks < 4; ks++) {
            const uint32_t kb = ks * 32;
            uint32_t av[4], bv[10][2];
            ldm_x4(st + a_base + kb, av[0], av[1], av[2], av[3]);
#pragma unroll
            for (int p = 0; p < 5; p++) {
                const uint32_t bo = b_base + p * 16 * CTX_PITCH + kb;
                ldm_x4(st + CTX_AOPB + bo,
                       bv[2 * p][0], bv[2 * p][1], bv[2 * p + 1][0], bv[2 * p + 1][1]);
            }
#pragma unroll
            for (int t2 = 0; t2 < 10; t2++) mma_fp16(acc[t2], av, bv[t2]);
        }
    }

    __syncthreads();
    float* sC = (float*)smem;
#pragma unroll
    for (int t2 = 0; t2 < 10; t2++) {
        const int r = lid >> 2;
        const int col = t2 * 8 + (lid & 3) * 2;
        sC[(wid * 16 + r) * 80 + col] = acc[t2][0];
        sC[(wid * 16 + r) * 80 + col + 1] = acc[t2][1];
        sC[(wid * 16 + r + 8) * 80 + col] = acc[t2][2];
        sC[(wid * 16 + r + 8) * 80 + col + 1] = acc[t2][3];
    }
    __syncthreads();
    const float* rsb = rsV + bh * DP_;
    for (int i = tid; i < 80 * 96; i += 192) {
        const int d = i / 96, m = i % 96;
        cT[((size_t)bh * DP_ + d) * MP_ + m0 + m] =
            __float2half(RATIO_ * (sC[m * 80 + d] + EPS_F * rsb[d]));
    }
}

// ------------- FUSED attn -----------------------------------------------------
#define AF_XS   0
#define AF_PROJ GA_OPB
#define AF_DIAG (GA_OPB + MP_ * PITCH)
#define AF_QF   (AF_DIAG + 512)
#define QPITCHB 592
#define AF_SMEM (AF_QF + 128 * QPITCHB)
#define AT_BOPB_F (80 * 112)

__global__ __launch_bounds__(256, 1) void attn_fused_kernel(
    const __half* __restrict__ QK, int ldq,
    const __half* __restrict__ projh,
    const __half* __restrict__ cT,
    __half* __restrict__ af) {
    extern __shared__ char smem[];
    const uint32_t sb = smem_u32(smem);
    float* diag_s = (float*)(smem + AF_DIAG);
    const int t = threadIdx.x;
    const int wid = t >> 5;
    const int lid = t & 31;
    const int bh = blockIdx.y;
    const int b = bh >> 4, h = bh & 15;
    const int n0 = blockIdx.x * 128;

    for (int i = t; i < 1024; i += 256) {
        const int r = i >> 3, seg = i & 7;
        *(uint4*)(smem + AF_XS + r * PITCH + seg * 16) =
            *(const uint4*)(QK + ((size_t)(b * N_ + n0 + r)) * ldq + h * 64 + seg * 8);
    }
    for (int e = t; e < MP_ * 8; e += 256) {
        const int r = e >> 3, seg = e & 7;
        *(uint4*)(smem + AF_PROJ + r * PITCH + seg * 16) =
            *(const uint4*)(projh + r * 64 + seg * 8);
    }
    __syncthreads();

    {
        const int row = t >> 1;
        const int halfsel = t & 1;
        const __half* rp = (const __half*)(smem + AF_XS + row * PITCH) + halfsel * 32;
        float dsum = 0.f;
#pragma unroll
        for (int j = 0; j < 32; j++) {
            const float v = __half2float(rp[j]);
            dsum += v * v;
        }
        dsum += __shfl_xor_sync(0xffffffffu, dsum, 1);
        if (halfsel == 0) diag_s[row] = 0.5f * dsum;
    }
    __syncthreads();

    const uint32_t a_base = (uint32_t)((wid * 16 + (lid & 15)) * PITCH + (lid >> 4) * 16);
    const uint32_t b_base = (uint32_t)((((lid >> 4) * 8) + (lid & 7)) * PITCH +
                                       ((lid >> 3) & 1) * 16);

    float acc[36][4];
#pragma unroll
    for (int t2 = 0; t2 < 36; t2++)
#pragma unroll
        for (int q = 0; q < 4; q++) acc[t2][q] = 0.f;

#pragma unroll
    for (int ks = 0; ks < 4; ks++) {
        const uint32_t kb = ks * 32;
        uint32_t av[4];
        ldm_x4(sb + AF_XS + a_base + kb, av[0], av[1], av[2], av[3]);
#pragma unroll
        for (int p = 0; p < 18; p++) {
            uint32_t bv[2][2];
            ldm_x4(sb + AF_PROJ + b_base + p * 16 * PITCH + kb,
                   bv[0][0], bv[0][1], bv[1][0], bv[1][1]);
            mma_fp16(acc[2 * p], av, bv[0]);
            mma_fp16(acc[2 * p + 1], av, bv[1]);
        }
    }

    const int g = lid >> 2, tg = lid & 3;
    float r0 = -1e30f, r1 = -1e30f;
#pragma unroll
    for (int t2 = 0; t2 < 36; t2++) {
        const int m = t2 * 8 + tg * 2;
        if (m < M_)     { r0 = fmaxf(r0, acc[t2][0]); r1 = fmaxf(r1, acc[t2][2]); }
        if (m + 1 < M_) { r0 = fmaxf(r0, acc[t2][1]); r1 = fmaxf(r1, acc[t2][3]); }
    }
    r0 = fmaxf(r0, __shfl_xor_sync(0xffffffffu, r0, 1));
    r0 = fmaxf(r0, __shfl_xor_sync(0xffffffffu, r0, 2));
    r1 = fmaxf(r1, __shfl_xor_sync(0xffffffffu, r1, 1));
    r1 = fmaxf(r1, __shfl_xor_sync(0xffffffffu, r1, 2));

    const int rowa = wid * 16 + g;
    const int rowb = rowa + 8;
    const float suba = diag_s[rowa] + r0;
    const float subb = diag_s[rowb] + r1;

    __half* qa = (__half*)(smem + AF_QF + rowa * QPITCHB);
    __half* qb = (__half*)(smem + AF_QF + rowb * QPITCHB);
#pragma unroll
    for (int t2 = 0; t2 < 36; t2++) {
        const int m = t2 * 8 + tg * 2;
        const float v0 = (m < M_)     ? RATIO_ * (expf(acc[t2][0] - suba) + EPS_F) : 0.f;
        const float v1 = (m + 1 < M_) ? RATIO_ * (expf(acc[t2][1] - suba) + EPS_F) : 0.f;
        const float v2 = (m < M_)     ? RATIO_ * (expf(acc[t2][2] - subb) + EPS_F) : 0.f;
        const float v3 = (m + 1 < M_) ? RATIO_ * (expf(acc[t2][3] - subb) + EPS_F) : 0.f;
        *(uint32_t*)(qa + m) = pack_half2(v0, v1);
        *(uint32_t*)(qb + m) = pack_half2(v2, v3);
    }
    __syncthreads();

    const __half* gB = cT + (size_t)bh * DP_ * MP_;
    const uint32_t aq_base = (uint32_t)(AF_QF + (wid * 16 + (lid & 15)) * QPITCHB +
                                        (lid >> 4) * 16);
    const uint32_t b2_base = (uint32_t)((((lid >> 4) * 8) + (lid & 7)) * 112 +
                                        ((lid >> 3) & 1) * 16);

    float acc2[10][4];
#pragma unroll
    for (int t2 = 0; t2 < 10; t2++)
#pragma unroll
        for (int q = 0; q < 4; q++) acc2[t2][q] = 0.f;

    auto issueB = [&](int c) {
        const uint32_t st = sb + (uint32_t)(c % 3) * AT_BOPB_F;
        const int k0 = c * 48;
        for (int i = t; i < 480; i += 256) {
            const int r = i / 6, cc = i % 6;
            cp16(st + r * 112 + cc * 16, gB + (size_t)r * MP_ + k0 + cc * 8);
        }
    };

    issueB(0); CP_COMMIT();
    issueB(1); CP_COMMIT();

    for (int c = 0; c < MP_ / 48; c++) {
        CP_WAIT(1);
        __syncthreads();
        if (c + 2 < MP_ / 48) issueB(c + 2);
        CP_COMMIT();

        const uint32_t st = sb + (uint32_t)(c % 3) * AT_BOPB_F;
        const uint32_t ak = (uint32_t)(c * 96);
#pragma unroll
        for (int ks = 0; ks < 3; ks++) {
            const uint32_t kb = ks * 32;
            uint32_t av[4], bv[10][2];
            ldm_x4(sb + aq_base + ak + kb, av[0], av[1], av[2], av[3]);
#pragma unroll
            for (int p = 0; p < 5; p++) {
                const uint32_t bo = b2_base + p * 16 * 112 + kb;
                ldm_x4(st + bo, bv[2 * p][0], bv[2 * p][1], bv[2 * p + 1][0], bv[2 * p + 1][1]);
            }
#pragma unroll
            for (int t2 = 0; t2 < 10; t2++) mma_fp16(acc2[t2], av, bv[t2]);
        }
    }

    const float den0 = __shfl_sync(0xffffffffu, acc2[8][0], lid & 28);
    const float den1 = __shfl_sync(0xffffffffu, acc2[8][2], lid & 28);
    const float rd0 = 1.f / den0;
    const float rd1 = 1.f / den1;

    const int nr = n0 + wid * 16 + (lid >> 2);
    const size_t base0 = (size_t)(b * N_ + nr) * D_ + h * 64;
    const size_t base1 = (size_t)(b * N_ + nr + 8) * D_ + h * 64;
#pragma unroll
    for (int t2 = 0; t2 < 8; t2++) {
        const int d = t2 * 8 + (lid & 3) * 2;
        *(uint32_t*)(af + base0 + d) = pack_half2(acc2[t2][0] * rd0, acc2[t2][1] * rd0);
        *(uint32_t*)(af + base1 + d) = pack_half2(acc2[t2][2] * rd1, acc2[t2][3] * rd1);
    }
}

// ------------------------- residual + LayerNorm (o2 fp16) -------------------
__global__ __launch_bounds__(256) void ln_kernel(const float* __restrict__ x,
                                                 const __half* __restrict__ o2,
                                                 const float* __restrict__ bo,
                                                 const float* __restrict__ gamma,
                                                 const float* __restrict__ beta,
                                                 float* __restrict__ out) {
    __shared__ float ss[256];
    __shared__ float sq[256];
    const int row = blockIdx.x;
    const int t = threadIdx.x;
    const size_t base = (size_t)row * D_;

    float yv[4];
    float s = 0.f, q = 0.f;
#pragma unroll
    for (int i = 0; i < 4; i++) {
        const int c = t + i * 256;
        const float v = x[base + c] + __half2float(o2[base + c]) + bo[c];
        yv[i] = v;
        s += v;
        q += v * v;
    }
    ss[t] = s;
    sq[t] = q;
    __syncthreads();
#pragma unroll
    for (int off = 128; off > 0; off >>= 1) {
        if (t < off) { ss[t] += ss[t + off]; sq[t] += sq[t + off]; }
        __syncthreads();
    }
    const float mu = ss[0] * (1.f / (float)D_);
    const float var = sq[0] * (1.f / (float)D_) - mu * mu;
    const float rstd = rsqrtf(var + EPS_LN);
#pragma unroll
    for (int i = 0; i < 4; i++) {
        const int c = t + i * 256;
        out[base + c] = (yv[i] - mu) * rstd * gamma[c] + beta[c];
    }
}

// ------------------------- launch --------------------------------------------
extern "C" void kernel_launch(void* const* d_in, const int* in_sizes, int n_in,
                              void* d_out, int out_size) {
    const float* x     = (const float*)d_in[0];
    const float* Wq    = (const float*)d_in[1];
    const float* Wk    = (const float*)d_in[2];
    const float* Wv    = (const float*)d_in[3];
    const float* Wo    = (const float*)d_in[4];
    const float* bo    = (const float*)d_in[5];
    const float* proj  = (const float*)d_in[6];
    const float* gamma = (const float*)d_in[7];
    const float* beta  = (const float*)d_in[8];
    float* out = (float*)d_out;

    float *pkd, *prm, *pkm, *prsV;
    __half *pQKV, *psfT, *pvT, *pcT, *paf, *po2h, *px16, *pWTqkv, *pWoT, *pprojh;
    cudaGetSymbolAddress((void**)&pkd,    g_kdiag);
    cudaGetSymbolAddress((void**)&prm,    g_krowmax);
    cudaGetSymbolAddress((void**)&pkm,    g_kmax);
    cudaGetSymbolAddress((void**)&prsV,   g_rsV);
    cudaGetSymbolAddress((void**)&pQKV,   g_QKV);
    cudaGetSymbolAddress((void**)&psfT,   g_sfT);
    cudaGetSymbolAddress((void**)&pvT,    g_vT);
    cudaGetSymbolAddress((void**)&pcT,    g_cT);
    cudaGetSymbolAddress((void**)&paf,    g_af);
    cudaGetSymbolAddress((void**)&po2h,   g_o2h);
    cudaGetSymbolAddress((void**)&px16,   g_x16);
    cudaGetSymbolAddress((void**)&pWTqkv, g_WTqkv);
    cudaGetSymbolAddress((void**)&pWoT,   g_WoT);
    cudaGetSymbolAddress((void**)&pprojh, g_projh);

    cudaFuncSetAttribute(gemm_fp16<__half>, cudaFuncAttributeMaxDynamicSharedMemorySize, GF_SMEM);
    cudaFuncSetAttribute(kfeat_mma_kernel, cudaFuncAttributeMaxDynamicSharedMemorySize, FEAT_SMEM);
    cudaFuncSetAttribute(ctx_mma_kernel, cudaFuncAttributeMaxDynamicSharedMemorySize, CTX_SMEM);
    cudaFuncSetAttribute(attn_fused_kernel, cudaFuncAttributeMaxDynamicSharedMemorySize, AF_SMEM);

    // 0. operand prep (DN_ folded into Wq/Wk so QKV outputs are xs directly)
    convert_x_h_kernel<<<BN_ * D_ / (256 * 4), 256>>>(x, px16);
    transT_all_kernel<<<dim3(32, 32, 4), dim3(32, 32)>>>(Wq, Wk, Wv, Wo, pWTqkv, pWoT);
    proj_pad_kernel<<<(MP_ * DH_ + 255) / 256, 256>>>(proj, pprojh);
    cudaMemsetAsync(prsV, 0, B_ * H_ * DP_ * sizeof(float));

    // 1. Fused QKV projection (fp16 in/out): C[16384][3072], 2 CTAs/SM
    gemm_fp16<__half><<<dim3(QKVW / 128, BN_ / 128), 128, GF_SMEM>>>(
        px16, pWTqkv, pQKV, QKVW);

    // 2. K features via MMA (K at col 1024); Q features fused into attn
    dim3 featGrid(N_ / 128, B_ * H_);
    kfeat_mma_kernel<<<featGrid, 256, FEAT_SMEM>>>(pQKV + 1024, QKVW, pprojh,
                                                   psfT, pkd, prm);
    kmax_reduce_kernel<<<B_ * H_, 256>>>(prm, pkm);

    // 3. scaled V^T + rowsumV (V at col 2048)
    vconvT_kernel<<<dim3(N_ / 32, B_ * H_), 256>>>(pQKV + 2048, QKVW,
                                                   pkd, prm, pkm, prsV, pvT);

    // 4. linear attention via tensor cores; qf computed inside attn
    ctx_mma_kernel<<<dim3(3, B_ * H_), 192, CTX_SMEM>>>(psfT, pvT, prsV, pcT);
    attn_fused_kernel<<<dim3(N_ / 128, B_ * H_), 256, AF_SMEM>>>(
        pQKV + 0, QKVW, pprojh, pcT, paf);

    // 5. Output projection (fp16 out) + residual + LayerNorm
    gemm_fp16<__half><<<dim3(D_ / 128, BN_ / 128), 128, GF_SMEM>>>(paf, pWoT, po2h, D_);
    ln_kernel<<<BN_, 256>>>(x, po2h, bo, gamma, beta, out);
}

// round 16
// speedup vs baseline: 1.0169x; 1.0169x over previous
#include <cuda_runtime.h>
#include <cuda_fp16.h>
#include <cstdint>
#include <cstddef>

// Problem constants
#define B_  4
#define N_  4096
#define H_  16
#define DH_ 64
#define M_  266
#define D_  1024
#define QKVW 3072
#define ROWS_ (B_*H_*N_)        // 262144
#define BN_   (B_*N_)           // 16384
#define MP_ 288                 // padded feature count
#define DP_ 80                  // padded head dim: 64 data + ones col + zeros

#define DN_    0.3535533906f
#define RATIO_ 0.0613139315f
#define EPS_F  1e-4f
#define EPS_LN 1e-5f

// ------------------------- scratch (device globals) -------------------------
__device__ float g_kdiag[ROWS_];
__device__ float g_krowmax[ROWS_];
__device__ float g_kmax[B_ * H_];
__device__ float g_rsV[B_ * H_ * DP_];

__device__ __half g_QKV[(size_t)BN_ * QKVW];          // fused Q|K|V output (fp16)
__device__ __half g_sfT[(size_t)B_ * H_ * MP_ * N_];  // sf^T [bh][m][n]
__device__ __half g_vT[(size_t)B_ * H_ * DP_ * N_];   // scaled V^T [bh][d][n]
__device__ __half g_cT[(size_t)B_ * H_ * DP_ * MP_];  // ctx^T [bh][d][m]
__device__ __half g_af[(size_t)BN_ * D_];             // attention out
__device__ __half g_o2h[(size_t)BN_ * D_];            // Wo output (fp16)
__device__ __half g_x16[(size_t)BN_ * D_];            // x fp16
__device__ __half g_WTqkv[(size_t)QKVW * D_];         // [Wq*DN|Wk*DN|Wv]^T fp16
__device__ __half g_WoT[(size_t)D_ * D_];             // Wo^T fp16
__device__ __half g_projh[MP_ * DH_];                 // proj fp16, zero-padded

// ------------------------- helpers ------------------------------------------
__device__ __forceinline__ uint32_t smem_u32(const void* p) {
    uint32_t a;
    asm("{ .reg .u64 t; cvta.to.shared.u64 t, %1; cvt.u32.u64 %0, t; }" : "=r"(a) : "l"(p));
    return a;
}
__device__ __forceinline__ void ldm_x4(uint32_t addr, uint32_t& r0, uint32_t& r1,
                                       uint32_t& r2, uint32_t& r3) {
    asm volatile("ldmatrix.sync.aligned.m8n8.x4.shared.b16 {%0,%1,%2,%3}, [%4];"
                 : "=r"(r0), "=r"(r1), "=r"(r2), "=r"(r3) : "r"(addr));
}
__device__ __forceinline__ void mma_fp16(float* c, const uint32_t* a, const uint32_t* b) {
    asm volatile(
        "mma.sync.aligned.m16n8k16.row.col.f32.f16.f16.f32 "
        "{%0,%1,%2,%3}, {%4,%5,%6,%7}, {%8,%9}, {%0,%1,%2,%3};"
        : "+f"(c[0]), "+f"(c[1]), "+f"(c[2]), "+f"(c[3])
        : "r"(a[0]), "r"(a[1]), "r"(a[2]), "r"(a[3]), "r"(b[0]), "r"(b[1]));
}
__device__ __forceinline__ void cp16(uint32_t saddr, const void* gptr) {
    asm volatile("cp.async.cg.shared.global [%0], [%1], 16;" :: "r"(saddr), "l"(gptr));
}
#define CP_COMMIT() asm volatile("cp.async.commit_group;" ::: "memory")
#define CP_WAIT(n)  asm volatile("cp.async.wait_group %0;" :: "n"(n) : "memory")

__device__ __forceinline__ uint32_t pack_half2(float a, float b) {
    __half2 t;
    t.x = __float2half(a);
    t.y = __float2half(b);
    return *reinterpret_cast<uint32_t*>(&t);
}

// ------------------------- prep kernels --------------------------------------
__global__ __launch_bounds__(256) void convert_x_h_kernel(const float* __restrict__ x,
                                                          __half* __restrict__ xh) {
    const size_t i = ((size_t)blockIdx.x * 256 + threadIdx.x) * 4;
    float4 v = *(const float4*)(x + i);
    uint2 o;
    o.x = pack_half2(v.x, v.y);
    o.y = pack_half2(v.z, v.w);
    *(uint2*)(xh + i) = o;
}

__global__ __launch_bounds__(1024) void transT_all_kernel(const float* __restrict__ W0,
                                                          const float* __restrict__ W1,
                                                          const float* __restrict__ W2,
                                                          const float* __restrict__ W3,
                                                          __half* __restrict__ WTqkv,
                                                          __half* __restrict__ WoT) {
    __shared__ float tile[32][33];
    const int z = blockIdx.z;
    const float* W = (z == 0) ? W0 : (z == 1) ? W1 : (z == 2) ? W2 : W3;
    __half* T = (z < 3) ? (WTqkv + (size_t)z * D_ * D_) : WoT;
    const float scale = (z < 2) ? DN_ : 1.f;

    const int n = blockIdx.x * 32 + threadIdx.x;
    const int k = blockIdx.y * 32 + threadIdx.y;
    tile[threadIdx.y][threadIdx.x] = W[(size_t)k * D_ + n];
    __syncthreads();
    const float v = tile[threadIdx.x][threadIdx.y] * scale;
    const int on = blockIdx.x * 32 + threadIdx.y;
    const int ok = blockIdx.y * 32 + threadIdx.x;
    T[(size_t)on * D_ + ok] = __float2half(v);
}

__global__ __launch_bounds__(256) void proj_pad_kernel(const float* __restrict__ proj,
                                                       __half* __restrict__ ph) {
    const int idx = blockIdx.x * 256 + threadIdx.x;
    if (idx >= MP_ * DH_) return;
    const int m = idx >> 6, k = idx & 63;
    ph[idx] = __float2half((m < M_) ? proj[m * 64 + k] : 0.f);
}

// ------ fp16 GEMM: CTA 128x128, warp 64x32, 3-stage, 2 CTAs/SM (round-13) ---
#define KC    64
#define PITCH 144
#define GA_OPB (128 * PITCH)          // 18432
#define GF_STAGE (2 * GA_OPB)         // 36864
#define GF_SMEM (3 * GF_STAGE)        // 110592

template <typename OutT>
__global__ __launch_bounds__(256, 2) void gemm_fp16(
    const __half* __restrict__ A, const __half* __restrict__ Bm,
    OutT* __restrict__ C, int ldc) {
    extern __shared__ char smem[];
    const uint32_t sb = smem_u32(smem);
    const int tid = threadIdx.x;
    const int wid = tid >> 5;
    const int lid = tid & 31;
    const int warp_m = wid & 1;       // 0..1 (64 rows)
    const int warp_n = wid >> 1;      // 0..3 (32 cols)
    const int row0 = blockIdx.y * 128;
    const int col0 = blockIdx.x * 128;

    const __half* gA = A + (size_t)row0 * D_;
    const __half* gB = Bm + (size_t)col0 * D_;

    const uint32_t a_base = (uint32_t)((warp_m * 64 + (lid & 15)) * PITCH + (lid >> 4) * 16);
    const uint32_t b_base = (uint32_t)((warp_n * 32 + ((lid >> 4) * 8) + (lid & 7)) * PITCH +
                                       ((lid >> 3) & 1) * 16);

    float acc[4][4][4];
#pragma unroll
    for (int mi = 0; mi < 4; mi++)
#pragma unroll
        for (int ni = 0; ni < 4; ni++)
#pragma unroll
            for (int q = 0; q < 4; q++) acc[mi][ni][q] = 0.f;

    auto issue = [&](int c) {
        const uint32_t st = sb + (uint32_t)(c % 3) * GF_STAGE;
        const int k0 = c * KC;
        for (int i = tid; i < 1024; i += 256) {
            const int r = i >> 3, cc = i & 7;
            cp16(st + r * PITCH + cc * 16, gA + (size_t)r * D_ + k0 + cc * 8);
            cp16(st + GA_OPB + r * PITCH + cc * 16, gB + (size_t)r * D_ + k0 + cc * 8);
        }
    };

    issue(0); CP_COMMIT();
    issue(1); CP_COMMIT();

    for (int c = 0; c < D_ / KC; c++) {
        CP_WAIT(1);
        __syncthreads();
        if (c + 2 < D_ / KC) issue(c + 2);
        CP_COMMIT();

        const uint32_t st = sb + (uint32_t)(c % 3) * GF_STAGE;
#pragma unroll
        for (int ks = 0; ks < 4; ks++) {
            const uint32_t kb = ks * 32;
            uint32_t av[4][4];
#pragma unroll
            for (int mi = 0; mi < 4; mi++) {
                const uint32_t ao = a_base + mi * 16 * PITCH + kb;
                ldm_x4(st + ao, av[mi][0], av[mi][1], av[mi][2], av[mi][3]);
            }
#pragma unroll
            for (int p = 0; p < 2; p++) {
                uint32_t bv[2][2];
                const uint32_t bo = b_base + p * 16 * PITCH + kb;
                ldm_x4(st + GA_OPB + bo, bv[0][0], bv[0][1], bv[1][0], bv[1][1]);
#pragma unroll
                for (int mi = 0; mi < 4; mi++)
#pragma unroll
                    for (int nn = 0; nn < 2; nn++)
                        mma_fp16(acc[mi][p * 2 + nn], av[mi], bv[nn]);
            }
        }
    }

    const int g = lid >> 2, tg = lid & 3;
#pragma unroll
    for (int mi = 0; mi < 4; mi++) {
#pragma unroll
        for (int ni = 0; ni < 4; ni++) {
            const int row = row0 + warp_m * 64 + mi * 16 + g;
            const int col = col0 + warp_n * 32 + ni * 8 + tg * 2;
            if constexpr (sizeof(OutT) == 2) {
                *(uint32_t*)((__half*)C + (size_t)row * ldc + col) =
                    pack_half2(acc[mi][ni][0], acc[mi][ni][1]);
                *(uint32_t*)((__half*)C + (size_t)(row + 8) * ldc + col) =
                    pack_half2(acc[mi][ni][2], acc[mi][ni][3]);
            } else {
                float2 v0 = {acc[mi][ni][0], acc[mi][ni][1]};
                float2 v1 = {acc[mi][ni][2], acc[mi][ni][3]};
                *(float2*)((float*)C + (size_t)row * ldc + col) = v0;
                *(float2*)((float*)C + (size_t)(row + 8) * ldc + col) = v1;
            }
        }
    }
}

// ------------------------- K-feature via MMA ----------------------------------
#define FA_A  0
#define FA_B  GA_OPB                       // 18432
#define FA_DIAG (GA_OPB + MP_ * PITCH)     // 59904
#define FEAT_SMEM (FA_DIAG + 128 * 4)      // 60416
#define TPITCH 136

__global__ __launch_bounds__(256, 1) void kfeat_mma_kernel(
    const __half* __restrict__ QK, int ldq,
    const __half* __restrict__ projh,
    __half* __restrict__ fout,
    float* __restrict__ diag_out, float* __restrict__ rowmax_out) {
    extern __shared__ char smem[];
    const uint32_t sb = smem_u32(smem);
    float* diag_s = (float*)(smem + FA_DIAG);
    const int t = threadIdx.x;
    const int wid = t >> 5;
    const int lid = t & 31;
    const int bh = blockIdx.y;
    const int b = bh >> 4, h = bh & 15;
    const int n0 = blockIdx.x * 128;
    const size_t idx0 = (size_t)bh * N_ + n0;

    for (int i = t; i < 1024; i += 256) {
        const int r = i >> 3, seg = i & 7;
        *(uint4*)(smem + FA_A + r * PITCH + seg * 16) =
            *(const uint4*)(QK + ((size_t)(b * N_ + n0 + r)) * ldq + h * 64 + seg * 8);
    }
    for (int e = t; e < MP_ * 8; e += 256) {
        const int r = e >> 3, seg = e & 7;
        *(uint4*)(smem + FA_B + r * PITCH + seg * 16) =
            *(const uint4*)(projh + r * 64 + seg * 8);
    }
    __syncthreads();

    {
        const int row = t >> 1;
        const int halfsel = t & 1;
        const __half* rp = (const __half*)(smem + FA_A + row * PITCH) + halfsel * 32;
        float dsum = 0.f;
#pragma unroll
        for (int j = 0; j < 32; j++) {
            const float v = __half2float(rp[j]);
            dsum += v * v;
        }
        dsum += __shfl_xor_sync(0xffffffffu, dsum, 1);
        if (halfsel == 0) diag_s[row] = 0.5f * dsum;
    }
    __syncthreads();

    const uint32_t a_base = (uint32_t)((wid * 16 + (lid & 15)) * PITCH + (lid >> 4) * 16);
    const uint32_t b_base = (uint32_t)((((lid >> 4) * 8) + (lid & 7)) * PITCH +
                                       ((lid >> 3) & 1) * 16);

    float acc[36][4];
#pragma unroll
    for (int t2 = 0; t2 < 36; t2++)
#pragma unroll
        for (int q = 0; q < 4; q++) acc[t2][q] = 0.f;

#pragma unroll
    for (int ks = 0; ks < 4; ks++) {
        const uint32_t kb = ks * 32;
        uint32_t av[4];
        ldm_x4(sb + FA_A + a_base + kb, av[0], av[1], av[2], av[3]);
#pragma unroll
        for (int p = 0; p < 18; p++) {
            uint32_t bv[2][2];
            ldm_x4(sb + FA_B + b_base + p * 16 * PITCH + kb,
                   bv[0][0], bv[0][1], bv[1][0], bv[1][1]);
            mma_fp16(acc[2 * p], av, bv[0]);
            mma_fp16(acc[2 * p + 1], av, bv[1]);
        }
    }

    const int g = lid >> 2, tg = lid & 3;
    float r0 = -1e30f, r1 = -1e30f;
#pragma unroll
    for (int t2 = 0; t2 < 36; t2++) {
        const int m = t2 * 8 + tg * 2;
        if (m < M_)     { r0 = fmaxf(r0, acc[t2][0]); r1 = fmaxf(r1, acc[t2][2]); }
        if (m + 1 < M_) { r0 = fmaxf(r0, acc[t2][1]); r1 = fmaxf(r1, acc[t2][3]); }
    }
    r0 = fmaxf(r0, __shfl_xor_sync(0xffffffffu, r0, 1));
    r0 = fmaxf(r0, __shfl_xor_sync(0xffffffffu, r0, 2));
    r1 = fmaxf(r1, __shfl_xor_sync(0xffffffffu, r1, 1));
    r1 = fmaxf(r1, __shfl_xor_sync(0xffffffffu, r1, 2));

    const int rowa = wid * 16 + g;
    const int rowb = rowa + 8;

    if (tg == 0) {
        rowmax_out[idx0 + rowa] = r0;
        rowmax_out[idx0 + rowb] = r1;
        diag_out[idx0 + rowa] = diag_s[rowa];
        diag_out[idx0 + rowb] = diag_s[rowb];
    }
    __half* sT = (__half*)smem;
#pragma unroll
    for (int p = 0; p < 2; p++) {
        __syncthreads();
#pragma unroll
        for (int t2 = 18 * p; t2 < 18 * p + 18; t2++) {
            const int m = t2 * 8 + tg * 2;
            const int mloc = m - p * 144;
            const float v0 = (m < M_)     ? expf(acc[t2][0] - r0) : 0.f;
            const float v1 = (m + 1 < M_) ? expf(acc[t2][1] - r0) : 0.f;
            const float v2 = (m < M_)     ? expf(acc[t2][2] - r1) : 0.f;
            const float v3 = (m + 1 < M_) ? expf(acc[t2][3] - r1) : 0.f;
            sT[mloc * TPITCH + rowa] = __float2half(v0);
            sT[(mloc + 1) * TPITCH + rowa] = __float2half(v1);
            sT[mloc * TPITCH + rowb] = __float2half(v2);
            sT[(mloc + 1) * TPITCH + rowb] = __float2half(v3);
        }
        __syncthreads();
        for (int i = t; i < 2304; i += 256) {
            const int r = i >> 4, cseg = i & 15;
            *(uint4*)(fout + ((size_t)bh * MP_ + p * 144 + r) * N_ + n0 + cseg * 8) =
                *(uint4*)(sT + r * TPITCH + cseg * 8);
        }
    }
}

__global__ __launch_bounds__(256) void kmax_reduce_kernel(const float* __restrict__ rowmax,
                                                          float* __restrict__ kmax) {
    __shared__ float sm[256];
    const int bh = blockIdx.x;
    float v = -1e30f;
    for (int i = threadIdx.x; i < N_; i += 256)
        v = fmaxf(v, rowmax[bh * N_ + i]);
    sm[threadIdx.x] = v;
    __syncthreads();
#pragma unroll
    for (int off = 128; off > 0; off >>= 1) {
        if (threadIdx.x < off) sm[threadIdx.x] = fmaxf(sm[threadIdx.x], sm[threadIdx.x + off]);
        __syncthreads();
    }
    if (threadIdx.x == 0) kmax[bh] = sm[0];
}

__global__ __launch_bounds__(256) void vconvT_kernel(const __half* __restrict__ V, int ldv,
                                                     const float* __restrict__ kdiag,
                                                     const float* __restrict__ rowmax,
                                                     const float* __restrict__ kmax,
                                                     float* __restrict__ rsV,
                                                     __half* __restrict__ vT) {
    __shared__ float sm[64][33];
    __shared__ float scale_s[32];
    __shared__ float dsum[DP_];
    const int bh = blockIdx.y;
    const int b = bh >> 4, h = bh & 15;
    const int n0 = blockIdx.x * 32;
    const int t = threadIdx.x;

#pragma unroll
    for (int q = 0; q < 8; q++) {
        const int idx = t + q * 256;
        const int d = idx & 63, j = idx >> 6;
        sm[d][j] = __half2float(V[((size_t)(b * N_ + n0 + j)) * ldv + h * 64 + d]);
    }
    if (t < 32) {
        const size_t ni = (size_t)bh * N_ + n0 + t;
        scale_s[t] = expf(rowmax[ni] - kdiag[ni] - kmax[bh]);
    }
    __syncthreads();

#pragma unroll
    for (int q = 0; q < 10; q++) {
        const int idx = t + q * 256;
        const int j = idx & 31, dd = idx >> 5;
        const float raw = (dd < 64) ? sm[dd][j] : ((dd == 64) ? 1.f : 0.f);
        float s = raw;
#pragma unroll
        for (int off = 16; off > 0; off >>= 1) s += __shfl_xor_sync(0xffffffffu, s, off);
        if (j == 0) dsum[dd] = s;
        vT[((size_t)bh * DP_ + dd) * N_ + n0 + j] = __float2half(raw * scale_s[j]);
    }
    __syncthreads();
    if (t < DP_) atomicAdd(&rsV[bh * DP_ + t], dsum[t]);
}

// ------------------------- ctx MMA ------------------------------------------
#define CTX_PITCH 144
#define CTX_AOPB (96 * CTX_PITCH)
#define CTX_BOPB (80 * CTX_PITCH)
#define CTX_STAGE (CTX_AOPB + CTX_BOPB)
#define CTX_SMEM (3 * CTX_STAGE)

__global__ __launch_bounds__(192, 1) void ctx_mma_kernel(
    const __half* __restrict__ sfT, const __half* __restrict__ vT,
    const float* __restrict__ rsV, __half* __restrict__ cT) {
    extern __shared__ char smem[];
    const uint32_t sb = smem_u32(smem);
    const int tid = threadIdx.x;
    const int wid = tid >> 5;
    const int lid = tid & 31;
    const int bh = blockIdx.y;
    const int m0 = blockIdx.x * 96;

    const __half* gA = sfT + ((size_t)bh * MP_ + m0) * N_;
    const __half* gB = vT + (size_t)bh * DP_ * N_;

    const uint32_t a_base = (uint32_t)((wid * 16 + (lid & 15)) * CTX_PITCH + (lid >> 4) * 16);
    const uint32_t b_base = (uint32_t)((((lid >> 4) * 8) + (lid & 7)) * CTX_PITCH +
                                       ((lid >> 3) & 1) * 16);

    float acc[10][4];
#pragma unroll
    for (int t2 = 0; t2 < 10; t2++)
#pragma unroll
        for (int q = 0; q < 4; q++) acc[t2][q] = 0.f;

    auto issue = [&](int c) {
        const uint32_t st = sb + (uint32_t)(c % 3) * CTX_STAGE;
        const int k0 = c * 64;
        for (int i = tid; i < 768; i += 192) {
            const int r = i >> 3, cc = i & 7;
            cp16(st + r * CTX_PITCH + cc * 16, gA + (size_t)r * N_ + k0 + cc * 8);
        }
        for (int i = tid; i < 640; i += 192) {
            const int r = i >> 3, cc = i & 7;
            cp16(st + CTX_AOPB + r * CTX_PITCH + cc * 16, gB + (size_t)r * N_ + k0 + cc * 8);
        }
    };

    issue(0); CP_COMMIT();
    issue(1); CP_COMMIT();

    for (int c = 0; c < N_ / 64; c++) {
        CP_WAIT(1);
        __syncthreads();
        if (c + 2 < N_ / 64) issue(c + 2);
        CP_COMMIT();

        const uint32_t st = sb + (uint32_t)(c % 3) * CTX_STAGE;
#pragma unroll
        for (int ks = 0; ks < 4; ks++) {
            const uint32_t kb = ks * 32;
            uint32_t av[4], bv[10][2];
            ldm_x4(st + a_base + kb, av[0], av[1], av[2], av[3]);
#pragma unroll
            for (int p = 0; p < 5; p++) {
                const uint32_t bo = b_base + p * 16 * CTX_PITCH + kb;
                ldm_x4(st + CTX_AOPB + bo,
                       bv[2 * p][0], bv[2 * p][1], bv[2 * p + 1][0], bv[2 * p + 1][1]);
            }
#pragma unroll
            for (int t2 = 0; t2 < 10; t2++) mma_fp16(acc[t2], av, bv[t2]);
        }
    }

    __syncthreads();
    float* sC = (float*)smem;
#pragma unroll
    for (int t2 = 0; t2 < 10; t2++) {
        const int r = lid >> 2;
        const int col = t2 * 8 + (lid & 3) * 2;
        sC[(wid * 16 + r) * 80 + col] = acc[t2][0];
        sC[(wid * 16 + r) * 80 + col + 1] = acc[t2][1];
        sC[(wid * 16 + r + 8) * 80 + col] = acc[t2][2];
        sC[(wid * 16 + r + 8) * 80 + col + 1] = acc[t2][3];
    }
    __syncthreads();
    const float* rsb = rsV + bh * DP_;
    for (int i = tid; i < 80 * 96; i += 192) {
        const int d = i / 96, m = i % 96;
        cT[((size_t)bh * DP_ + d) * MP_ + m0 + m] =
            __float2half(RATIO_ * (sC[m * 80 + d] + EPS_F * rsb[d]));
    }
}

// ------------- FUSED attn -----------------------------------------------------
#define AF_XS   0
#define AF_PROJ GA_OPB
#define AF_DIAG (GA_OPB + MP_ * PITCH)
#define AF_QF   (AF_DIAG + 512)
#define QPITCHB 592
#define AF_SMEM (AF_QF + 128 * QPITCHB)
#define AT_BOPB_F (80 * 112)

__global__ __launch_bounds__(256, 1) void attn_fused_kernel(
    const __half* __restrict__ QK, int ldq,
    const __half* __restrict__ projh,
    const __half* __restrict__ cT,
    __half* __restrict__ af) {
    extern __shared__ char smem[];
    const uint32_t sb = smem_u32(smem);
    float* diag_s = (float*)(smem + AF_DIAG);
    const int t = threadIdx.x;
    const int wid = t >> 5;
    const int lid = t & 31;
    const int bh = blockIdx.y;
    const int b = bh >> 4, h = bh & 15;
    const int n0 = blockIdx.x * 128;

    for (int i = t; i < 1024; i += 256) {
        const int r = i >> 3, seg = i & 7;
        *(uint4*)(smem + AF_XS + r * PITCH + seg * 16) =
            *(const uint4*)(QK + ((size_t)(b * N_ + n0 + r)) * ldq + h * 64 + seg * 8);
    }
    for (int e = t; e < MP_ * 8; e += 256) {
        const int r = e >> 3, seg = e & 7;
        *(uint4*)(smem + AF_PROJ + r * PITCH + seg * 16) =
            *(const uint4*)(projh + r * 64 + seg * 8);
    }
    __syncthreads();

    {
        const int row = t >> 1;
        const int halfsel = t & 1;
        const __half* rp = (const __half*)(smem + AF_XS + row * PITCH) + halfsel * 32;
        float dsum = 0.f;
#pragma unroll
        for (int j = 0; j < 32; j++) {
            const float v = __half2float(rp[j]);
            dsum += v * v;
        }
        dsum += __shfl_xor_sync(0xffffffffu, dsum, 1);
        if (halfsel == 0) diag_s[row] = 0.5f * dsum;
    }
    __syncthreads();

    const uint32_t a_base = (uint32_t)((wid * 16 + (lid & 15)) * PITCH + (lid >> 4) * 16);
    const uint32_t b_base = (uint32_t)((((lid >> 4) * 8) + (lid & 7)) * PITCH +
                                       ((lid >> 3) & 1) * 16);

    float acc[36][4];
#pragma unroll
    for (int t2 = 0; t2 < 36; t2++)
#pragma unroll
        for (int q = 0; q < 4; q++) acc[t2][q] = 0.f;

#pragma unroll
    for (int ks = 0; ks < 4; ks++) {
        const uint32_t kb = ks * 32;
        uint32_t av[4];
        ldm_x4(sb + AF_XS + a_base + kb, av[0], av[1], av[2], av[3]);
#pragma unroll
        for (int p = 0; p < 18; p++) {
            uint32_t bv[2][2];
            ldm_x4(sb + AF_PROJ + b_base + p * 16 * PITCH + kb,
                   bv[0][0], bv[0][1], bv[1][0], bv[1][1]);
            mma_fp16(acc[2 * p], av, bv[0]);
            mma_fp16(acc[2 * p + 1], av, bv[1]);
        }
    }

    const int g = lid >> 2, tg = lid & 3;
    float r0 = -1e30f, r1 = -1e30f;
#pragma unroll
    for (int t2 = 0; t2 < 36; t2++) {
        const int m = t2 * 8 + tg * 2;
        if (m < M_)     { r0 = fmaxf(r0, acc[t2][0]); r1 = fmaxf(r1, acc[t2][2]); }
        if (m + 1 < M_) { r0 = fmaxf(r0, acc[t2][1]); r1 = fmaxf(r1, acc[t2][3]); }
    }
    r0 = fmaxf(r0, __shfl_xor_sync(0xffffffffu, r0, 1));
    r0 = fmaxf(r0, __shfl_xor_sync(0xffffffffu, r0, 2));
    r1 = fmaxf(r1, __shfl_xor_sync(0xffffffffu, r1, 1));
    r1 = fmaxf(r1, __shfl_xor_sync(0xffffffffu, r1, 2));

    const int rowa = wid * 16 + g;
    const int rowb = rowa + 8;
    const float suba = diag_s[rowa] + r0;
    const float subb = diag_s[rowb] + r1;

    __half* qa = (__half*)(smem + AF_QF + rowa * QPITCHB);
    __half* qb = (__half*)(smem + AF_QF + rowb * QPITCHB);
#pragma unroll
    for (int t2 = 0; t2 < 36; t2++) {
        const int m = t2 * 8 + tg * 2;
        const float v0 = (m < M_)     ? RATIO_ * (expf(acc[t2][0] - suba) + EPS_F) : 0.f;
        const float v1 = (m + 1 < M_) ? RATIO_ * (expf(acc[t2][1] - suba) + EPS_F) : 0.f;
        const float v2 = (m < M_)     ? RATIO_ * (expf(acc[t2][2] - subb) + EPS_F) : 0.f;
        const float v3 = (m + 1 < M_) ? RATIO_ * (expf(acc[t2][3] - subb) + EPS_F) : 0.f;
        *(uint32_t*)(qa + m) = pack_half2(v0, v1);
        *(uint32_t*)(qb + m) = pack_half2(v2, v3);
    }
    __syncthreads();

    const __half* gB = cT + (size_t)bh * DP_ * MP_;
    const uint32_t aq_base = (uint32_t)(AF_QF + (wid * 16 + (lid & 15)) * QPITCHB +
                                        (lid >> 4) * 16);
    const uint32_t b2_base = (uint32_t)((((lid >> 4) * 8) + (lid & 7)) * 112 +
                                        ((lid >> 3) & 1) * 16);

    float acc2[10][4];
#pragma unroll
    for (int t2 = 0; t2 < 10; t2++)
#pragma unroll
        for (int q = 0; q < 4; q++) acc2[t2][q] = 0.f;

    auto issueB = [&](int c) {
        const uint32_t st = sb + (uint32_t)(c % 3) * AT_BOPB_F;
        const int k0 = c * 48;
        for (int i = t; i < 480; i += 256) {
            const int r = i / 6, cc = i % 6;
            cp16(st + r * 112 + cc * 16, gB + (size_t)r * MP_ + k0 + cc * 8);
        }
    };

    issueB(0); CP_COMMIT();
    issueB(1); CP_COMMIT();

    for (int c = 0; c < MP_ / 48; c++) {
        CP_WAIT(1);
        __syncthreads();
        if (c + 2 < MP_ / 48) issueB(c + 2);
        CP_COMMIT();

        const uint32_t st = sb + (uint32_t)(c % 3) * AT_BOPB_F;
        const uint32_t ak = (uint32_t)(c * 96);
#pragma unroll
        for (int ks = 0; ks < 3; ks++) {
            const uint32_t kb = ks * 32;
            uint32_t av[4], bv[10][2];
            ldm_x4(sb + aq_base + ak + kb, av[0], av[1], av[2], av[3]);
#pragma unroll
            for (int p = 0; p < 5; p++) {
                const uint32_t bo = b2_base + p * 16 * 112 + kb;
                ldm_x4(st + bo, bv[2 * p][0], bv[2 * p][1], bv[2 * p + 1][0], bv[2 * p + 1][1]);
            }
#pragma unroll
            for (int t2 = 0; t2 < 10; t2++) mma_fp16(acc2[t2], av, bv[t2]);
        }
    }

    const float den0 = __shfl_sync(0xffffffffu, acc2[8][0], lid & 28);
    const float den1 = __shfl_sync(0xffffffffu, acc2[8][2], lid & 28);
    const float rd0 = 1.f / den0;
    const float rd1 = 1.f / den1;

    const int nr = n0 + wid * 16 + (lid >> 2);
    const size_t base0 = (size_t)(b * N_ + nr) * D_ + h * 64;
    const size_t base1 = (size_t)(b * N_ + nr + 8) * D_ + h * 64;
#pragma unroll
    for (int t2 = 0; t2 < 8; t2++) {
        const int d = t2 * 8 + (lid & 3) * 2;
        *(uint32_t*)(af + base0 + d) = pack_half2(acc2[t2][0] * rd0, acc2[t2][1] * rd0);
        *(uint32_t*)(af + base1 + d) = pack_half2(acc2[t2][2] * rd1, acc2[t2][3] * rd1);
    }
}

// ------------------------- residual + LayerNorm (o2 fp16) -------------------
__global__ __launch_bounds__(256) void ln_kernel(const float* __restrict__ x,
                                                 const __half* __restrict__ o2,
                                                 const float* __restrict__ bo,
                                                 const float* __restrict__ gamma,
                                                 const float* __restrict__ beta,
                                                 float* __restrict__ out) {
    __shared__ float ss[256];
    __shared__ float sq[256];
    const int row = blockIdx.x;
    const int t = threadIdx.x;
    const size_t base = (size_t)row * D_;

    float yv[4];
    float s = 0.f, q = 0.f;
#pragma unroll
    for (int i = 0; i < 4; i++) {
        const int c = t + i * 256;
        const float v = x[base + c] + __half2float(o2[base + c]) + bo[c];
        yv[i] = v;
        s += v;
        q += v * v;
    }
    ss[t] = s;
    sq[t] = q;
    __syncthreads();
#pragma unroll
    for (int off = 128; off > 0; off >>= 1) {
        if (t < off) { ss[t] += ss[t + off]; sq[t] += sq[t + off]; }
        __syncthreads();
    }
    const float mu = ss[0] * (1.f / (float)D_);
    const float var = sq[0] * (1.f / (float)D_) - mu * mu;
    const float rstd = rsqrtf(var + EPS_LN);
#pragma unroll
    for (int i = 0; i < 4; i++) {
        const int c = t + i * 256;
        out[base + c] = (yv[i] - mu) * rstd * gamma[c] + beta[c];
    }
}

// ------------------------- launch --------------------------------------------
extern "C" void kernel_launch(void* const* d_in, const int* in_sizes, int n_in,
                              void* d_out, int out_size) {
    const float* x     = (const float*)d_in[0];
    const float* Wq    = (const float*)d_in[1];
    const float* Wk    = (const float*)d_in[2];
    const float* Wv    = (const float*)d_in[3];
    const float* Wo    = (const float*)d_in[4];
    const float* bo    = (const float*)d_in[5];
    const float* proj  = (const float*)d_in[6];
    const float* gamma = (const float*)d_in[7];
    const float* beta  = (const float*)d_in[8];
    float* out = (float*)d_out;

    float *pkd, *prm, *pkm, *prsV;
    __half *pQKV, *psfT, *pvT, *pcT, *paf, *po2h, *px16, *pWTqkv, *pWoT, *pprojh;
    cudaGetSymbolAddress((void**)&pkd,    g_kdiag);
    cudaGetSymbolAddress((void**)&prm,    g_krowmax);
    cudaGetSymbolAddress((void**)&pkm,    g_kmax);
    cudaGetSymbolAddress((void**)&prsV,   g_rsV);
    cudaGetSymbolAddress((void**)&pQKV,   g_QKV);
    cudaGetSymbolAddress((void**)&psfT,   g_sfT);
    cudaGetSymbolAddress((void**)&pvT,    g_vT);
    cudaGetSymbolAddress((void**)&pcT,    g_cT);
    cudaGetSymbolAddress((void**)&paf,    g_af);
    cudaGetSymbolAddress((void**)&po2h,   g_o2h);
    cudaGetSymbolAddress((void**)&px16,   g_x16);
    cudaGetSymbolAddress((void**)&pWTqkv, g_WTqkv);
    cudaGetSymbolAddress((void**)&pWoT,   g_WoT);
    cudaGetSymbolAddress((void**)&pprojh, g_projh);

    cudaFuncSetAttribute(gemm_fp16<__half>, cudaFuncAttributeMaxDynamicSharedMemorySize, GF_SMEM);
    cudaFuncSetAttribute(kfeat_mma_kernel, cudaFuncAttributeMaxDynamicSharedMemorySize, FEAT_SMEM);
    cudaFuncSetAttribute(ctx_mma_kernel, cudaFuncAttributeMaxDynamicSharedMemorySize, CTX_SMEM);
    cudaFuncSetAttribute(attn_fused_kernel, cudaFuncAttributeMaxDynamicSharedMemorySize, AF_SMEM);

    // 0. operand prep (DN_ folded into Wq/Wk so QKV outputs are xs directly)
    convert_x_h_kernel<<<BN_ * D_ / (256 * 4), 256>>>(x, px16);
    transT_all_kernel<<<dim3(32, 32, 4), dim3(32, 32)>>>(Wq, Wk, Wv, Wo, pWTqkv, pWoT);
    proj_pad_kernel<<<(MP_ * DH_ + 255) / 256, 256>>>(proj, pprojh);
    cudaMemsetAsync(prsV, 0, B_ * H_ * DP_ * sizeof(float));

    // 1. Fused QKV projection (fp16 in/out): C[16384][3072], 2 CTAs/SM
    gemm_fp16<__half><<<dim3(QKVW / 128, BN_ / 128), 256, GF_SMEM>>>(
        px16, pWTqkv, pQKV, QKVW);

    // 2. K features via MMA (K at col 1024); Q features fused into attn
    dim3 featGrid(N_ / 128, B_ * H_);
    kfeat_mma_kernel<<<featGrid, 256, FEAT_SMEM>>>(pQKV + 1024, QKVW, pprojh,
                                                   psfT, pkd, prm);
    kmax_reduce_kernel<<<B_ * H_, 256>>>(prm, pkm);

    // 3. scaled V^T + rowsumV (V at col 2048)
    vconvT_kernel<<<dim3(N_ / 32, B_ * H_), 256>>>(pQKV + 2048, QKVW,
                                                   pkd, prm, pkm, prsV, pvT);

    // 4. linear attention via tensor cores; qf computed inside attn
    ctx_mma_kernel<<<dim3(3, B_ * H_), 192, CTX_SMEM>>>(psfT, pvT, prsV, pcT);
    attn_fused_kernel<<<dim3(N_ / 128, B_ * H_), 256, AF_SMEM>>>(
        pQKV + 0, QKVW, pprojh, pcT, paf);

    // 5. Output projection (fp16 out) + residual + LayerNorm
    gemm_fp16<__half><<<dim3(D_ / 128, BN_ / 128), 256, GF_SMEM>>>(paf, pWoT, po2h, D_);
    ln_kernel<<<BN_, 256>>>(x, po2h, bo, gamma, beta, out);
}